// round 2
// baseline (speedup 1.0000x reference)
#include <cuda_runtime.h>
#include <math.h>

#define POOL 7
#define ROI_SCALE 0.0625f
#define WPB 8   // warps per block

// One warp per (n, c) feature plane. Lanes are x-columns of the ROI:
// lane covers x = px+lane (and px+lane+32 when ROI is wider than 32).
// For each of the 7 row-bins: lanes compute column maxima over the bin's rows
// with fully coalesced row loads, dump to per-warp smem, then 7 lanes do the
// x-direction segmented max and write out[n][c][ph][pw].
__global__ __launch_bounds__(32 * WPB)
void roipool_warp_kernel(const float* __restrict__ feat,
                         const float* __restrict__ rois,
                         float* __restrict__ out,
                         int N, int C, int H, int W, int write_bid) {
    __shared__ float colmax[WPB][64];

    int warp = threadIdx.x >> 5;
    int lane = threadIdx.x & 31;
    int w = blockIdx.x * WPB + warp;           // w = n*C + c

    // Fused second output of the reference tuple: batch ids as floats.
    if (write_bid) {
        int t = blockIdx.x * blockDim.x + threadIdx.x;
        if (t < N) out[(size_t)N * C * POOL * POOL + t] = (float)((int)rois[t * 5]);
    }

    if (w >= N * C) return;
    int n = w / C;

    const float* r = rois + n * 5;
    int b  = (int)r[0];
    // jnp.round = round-half-to-even = __float2int_rn
    int px = __float2int_rn(r[1] * ROI_SCALE);
    int py = __float2int_rn(r[2] * ROI_SCALE);
    int qx = __float2int_rn(r[3] * ROI_SCALE);
    int qy = __float2int_rn(r[4] * ROI_SCALE);

    int lenx = max(qx - px + 1, 1);
    int leny = max(qy - py + 1, 1);
    int psx  = (lenx + POOL - 1) / POOL;
    int psy  = (leny + POOL - 1) / POOL;
    int pad0x = (psx * POOL - lenx) / 2;
    int pad0y = (psy * POOL - leny) / 2;

    const float* fc = feat + (size_t)(b * C + (w - n * C)) * H * W;

    // Per-lane column assignment (clamped addresses stay in-bounds; inactive
    // lanes' values are masked to -INF before the reduce).
    int rx1 = min(lane, lenx - 1);
    int rx2 = min(lane + 32, lenx - 1);
    bool a1 = lane < lenx;
    bool a2 = lane + 32 < lenx;
    const float* col1 = fc + px + rx1;
    const float* col2 = fc + px + rx2;
    bool two = lenx > 32;   // uniform per warp

    float* cm = colmax[warp];

    for (int ph = 0; ph < POOL; ++ph) {
        // rows of this bin, in ROI-relative coords, clipped to the real crop
        int ys = max(0, ph * psy - pad0y);
        int ye = min(leny - 1, (ph + 1) * psy - 1 - pad0y);

        float m1 = -INFINITY, m2 = -INFINITY;
        if (two) {
            #pragma unroll 2
            for (int ry = ys; ry <= ye; ++ry) {
                int off = (py + ry) * W;
                m1 = fmaxf(m1, __ldg(col1 + off));
                m2 = fmaxf(m2, __ldg(col2 + off));
            }
        } else {
            #pragma unroll 2
            for (int ry = ys; ry <= ye; ++ry) {
                int off = (py + ry) * W;
                m1 = fmaxf(m1, __ldg(col1 + off));
            }
        }

        cm[lane]      = a1 ? m1 : -INFINITY;
        cm[lane + 32] = a2 ? m2 : -INFINITY;
        __syncwarp();

        if (lane < POOL) {
            int pw = lane;
            float mm = -INFINITY;
            int x0 = pw * psx - pad0x;
            for (int i = 0; i < psx; ++i) {
                int rx = x0 + i;
                if (rx >= 0 && rx < lenx) mm = fmaxf(mm, cm[rx]);
            }
            bool padx = (pw * psx < pad0x) | ((pw + 1) * psx > pad0x + lenx);
            bool pady = (ph * psy < pad0y) | ((ph + 1) * psy > pad0y + leny);
            if (padx | pady) mm = fmaxf(mm, 0.0f);
            if (!isfinite(mm)) mm = 0.0f;   // fully-padded bin -> 0
            out[((size_t)w * POOL + ph) * POOL + pw] = mm;
        }
        __syncwarp();
    }
}

extern "C" void kernel_launch(void* const* d_in, const int* in_sizes, int n_in,
                              void* d_out, int out_size) {
    const float* feat = (const float*)d_in[0];
    const float* rois = (const float*)d_in[1];
    float* out = (float*)d_out;

    const int C = 256, H = 64, W = 64;
    int N = in_sizes[1] / 5;

    int total = N * C * POOL * POOL;
    int write_bid = (out_size >= total + N) ? 1 : 0;

    int nwarps = N * C;
    int blocks = (nwarps + WPB - 1) / WPB;
    roipool_warp_kernel<<<blocks, 32 * WPB>>>(feat, rois, out, N, C, H, W, write_bid);
}

// round 3
// speedup vs baseline: 2.0127x; 2.0127x over previous
#include <cuda_runtime.h>
#include <math.h>

#define POOL 7
#define ROI_SCALE 0.0625f
#define WPB 4        // warps per block
#define CH  4        // channels per warp

// One warp handles CH=4 channel planes of one ROI.
// Phase 1: single pass over the ROI's rows. Lanes cover x via float2 loads
//   (64 columns per warp-LDG). Running column-max per channel; flushed to
//   smem at each row-bin boundary (incremental tracking, no division in loop).
// Phase 2: all 4*49 output bins distributed across the 32 lanes; each bin
//   does the x-direction segmented max from smem.
__global__ __launch_bounds__(32 * WPB)
void roipool_kernel(const float* __restrict__ feat,
                    const float* __restrict__ rois,
                    float* __restrict__ out,
                    int N, int C, int write_bid) {
    __shared__ float cm[WPB][CH][POOL][64];
    const int H = 64, W = 64;

    int warp = threadIdx.x >> 5;
    int lane = threadIdx.x & 31;
    int NG = C / CH;
    int w = blockIdx.x * WPB + warp;          // w = n*NG + cg

    // Fused second output of the reference tuple: batch ids as floats.
    if (write_bid && blockIdx.x == 0 && threadIdx.x < N) {
        out[(size_t)N * C * POOL * POOL + threadIdx.x] =
            (float)((int)rois[threadIdx.x * 5]);
    }
    if (w >= N * NG) return;
    int n  = w / NG;
    int cg = w - n * NG;

    const float* r = rois + n * 5;
    int b  = (int)r[0];
    // jnp.round = round-half-to-even = __float2int_rn
    int px = __float2int_rn(r[1] * ROI_SCALE);
    int py = __float2int_rn(r[2] * ROI_SCALE);
    int qx = __float2int_rn(r[3] * ROI_SCALE);
    int qy = __float2int_rn(r[4] * ROI_SCALE);

    int lenx = max(qx - px + 1, 1);
    int leny = max(qy - py + 1, 1);
    int psx  = (lenx + POOL - 1) / POOL;
    int psy  = (leny + POOL - 1) / POOL;
    int pad0x = (psx * POOL - lenx) / 2;
    int pad0y = (psy * POOL - leny) / 2;
    int phf = pad0y / psy;                       // first row-bin with data
    int phl = (pad0y + leny - 1) / psy;          // last row-bin with data

    int px2 = px & ~1;                           // even-aligned load base
    int dpx = px - px2;                          // 0 or 1
    bool act = (px2 + 2 * lane) <= qx;           // this lane's float2 needed?

    const float2* p2 = (const float2*)(feat
        + (size_t)(b * C + cg * CH) * H * W + py * W + px2) + lane;
    const int PLANE2 = H * W / 2;                // plane stride in float2

    float2 a0 = make_float2(-INFINITY, -INFINITY);
    float2 a1 = a0, a2 = a0, a3 = a0;

    int ph   = phf;
    int ry_b = (phf + 1) * psy - pad0y;          // next bin boundary (>=1)

    float* cw = &cm[warp][0][0][0];              // [CH][7][64]
    int si = 2 * lane;                           // even smem index -> STS.64 ok

    for (int ry = 0; ry < leny; ++ry) {
        if (ry == ry_b) {                        // warp-uniform, rare
            *(float2*)(cw + (0 * POOL + ph) * 64 + si) = a0;
            *(float2*)(cw + (1 * POOL + ph) * 64 + si) = a1;
            *(float2*)(cw + (2 * POOL + ph) * 64 + si) = a2;
            *(float2*)(cw + (3 * POOL + ph) * 64 + si) = a3;
            a0 = a1 = a2 = a3 = make_float2(-INFINITY, -INFINITY);
            ++ph;
            ry_b += psy;
        }
        if (act) {
            float2 v0 = __ldg(p2);
            float2 v1 = __ldg(p2 + PLANE2);
            float2 v2 = __ldg(p2 + 2 * PLANE2);
            float2 v3 = __ldg(p2 + 3 * PLANE2);
            a0.x = fmaxf(a0.x, v0.x); a0.y = fmaxf(a0.y, v0.y);
            a1.x = fmaxf(a1.x, v1.x); a1.y = fmaxf(a1.y, v1.y);
            a2.x = fmaxf(a2.x, v2.x); a2.y = fmaxf(a2.y, v2.y);
            a3.x = fmaxf(a3.x, v3.x); a3.y = fmaxf(a3.y, v3.y);
        }
        p2 += W / 2;
    }
    // final flush
    *(float2*)(cw + (0 * POOL + ph) * 64 + si) = a0;
    *(float2*)(cw + (1 * POOL + ph) * 64 + si) = a1;
    *(float2*)(cw + (2 * POOL + ph) * 64 + si) = a2;
    *(float2*)(cw + (3 * POOL + ph) * 64 + si) = a3;
    __syncwarp();

    // Phase 2: CH*49 = 196 bins across 32 lanes
    size_t obase = (size_t)(n * C + cg * CH) * POOL * POOL;
    for (int bi = lane; bi < CH * POOL * POOL; bi += 32) {
        int ch  = bi / (POOL * POOL);
        int rem = bi - ch * POOL * POOL;
        int phb = rem / POOL;
        int pw  = rem - phb * POOL;

        float mm = -INFINITY;
        if (phb >= phf && phb <= phl) {
            int x0 = pw * psx - pad0x;
            int i0 = max(0, -x0);
            int i1 = min(psx, lenx - x0);
            const float* row = cw + (ch * POOL + phb) * 64 + x0 + dpx;
            for (int i = i0; i < i1; ++i)
                mm = fmaxf(mm, row[i]);
        }
        bool padx = (pw * psx < pad0x) | ((pw + 1) * psx > pad0x + lenx);
        bool pady = (phb * psy < pad0y) | ((phb + 1) * psy > pad0y + leny);
        if (padx | pady) mm = fmaxf(mm, 0.0f);
        if (!isfinite(mm)) mm = 0.0f;            // fully-padded bin -> 0
        out[obase + (size_t)ch * POOL * POOL + rem] = mm;
    }
}

extern "C" void kernel_launch(void* const* d_in, const int* in_sizes, int n_in,
                              void* d_out, int out_size) {
    const float* feat = (const float*)d_in[0];
    const float* rois = (const float*)d_in[1];
    float* out = (float*)d_out;

    const int C = 256;
    int N = in_sizes[1] / 5;

    int total = N * C * POOL * POOL;
    int write_bid = (out_size >= total + N) ? 1 : 0;

    int nwarps = N * (C / CH);
    int blocks = (nwarps + WPB - 1) / WPB;
    roipool_kernel<<<blocks, 32 * WPB>>>(feat, rois, out, N, C, write_bid);
}